// round 11
// baseline (speedup 1.0000x reference)
#include <cuda_runtime.h>
#include <cuda_fp16.h>
#include <math.h>

// ---------------------------------------------------------------------------
// NonstationaryGaussianSpectralMixtureKernel
// Phase 1 (per point): u = A*cos(2pi ph), v = A*sin(2pi ph), s2 = s^2,
//   A = w*sqrt(s)*2^(1/4);  coords stored pre-scaled by sqrt(log2e).
// Phase 2: K[i,j] = sum_q (uX uY + vX vY) * [r * exp2(-d2*r)],
//   r = 1/(s2X+s2Y).  The bracketed product is computed entirely in fp16x2:
//   HADD2 + magic-Halley rcp + HMUL2 + ex2.f16x2 (1 MUFU / 2 pairs) + HMUL2.
// Phases linked by Programmatic Dependent Launch (no inter-kernel gap).
// ---------------------------------------------------------------------------

#define MAXPTS 8192
// [side][row][point]; rows: q->u, 8+q->v, 16+q->s2, 24..26 -> scaled coords
__device__ float g_feat[2][27][MAXPTS];

__device__ __forceinline__ float fex2_fast(float x) {
    float r; asm("ex2.approx.f32 %0, %1;" : "=f"(r) : "f"(x)); return r;
}
__device__ __forceinline__ float flg2_fast(float x) {
    float r; asm("lg2.approx.f32 %0, %1;" : "=f"(r) : "f"(x)); return r;
}

// fp16x2 reciprocal: per-half magic seed + one Halley step.
// Valid for s2 in [6e-5, ~24000] (no cross-half borrow, no subnormals).
__device__ __forceinline__ __half2 h2rcp_cubic(__half2 x) {
    unsigned int xb = *reinterpret_cast<unsigned int*>(&x);
    unsigned int rb = 0x779D779Du - xb;
    __half2 r0 = *reinterpret_cast<__half2*>(&rb);
    __half2 t  = __hmul2(x, r0);
    const __half2 h3  = __float2half2_rn(3.0f);
    const __half2 hn3 = __float2half2_rn(-3.0f);
    __half2 p  = __hfma2(t, t, __hfma2(hn3, t, h3));
    return __hmul2(r0, p);
}

__device__ __forceinline__ float selu_f(float x) {
    const float scale = 1.0507009873554805f;
    const float sa    = 1.7580993408473766f;   // scale*alpha
    const float LOG2E = 1.4426950408889634f;
    float em1 = fex2_fast(x * LOG2E) - 1.0f;
    return (x > 0.0f) ? scale * x : sa * em1;
}
__device__ __forceinline__ float softplus_f(float x) {
    const float LOG2E = 1.4426950408889634f;
    const float LN2   = 0.6931471805599453f;
    float e = fex2_fast(-fabsf(x) * LOG2E);
    return fmaxf(x, 0.0f) + LN2 * flg2_fast(1.0f + e);
}

// ---------------------------------------------------------------------------
// Phase 1: 8 threads per point (one per q), 32 points per 256-thread block.
// ---------------------------------------------------------------------------
__global__ void __launch_bounds__(256)
feat_kernel(
    const float* __restrict__ x, const float* __restrict__ y,
    const float* __restrict__ W1, const float* __restrict__ b1,
    const float* __restrict__ Ww, const float* __restrict__ bw,
    const float* __restrict__ Wf, const float* __restrict__ bf,
    const float* __restrict__ Ws, const float* __restrict__ bs,
    int N, int M)
{
    __shared__ float sW1[64 * 3];
    __shared__ float sb1[64];
    __shared__ float sHw[64][9];
    __shared__ float sHs[64][9];
    __shared__ float sHf[64][25];
    __shared__ float sbw[8], sbs[8], sbf[24];
    __shared__ float sh_h[32][65];

    int tid = threadIdx.x;
    for (int i = tid; i < 64 * 3; i += 256) sW1[i] = W1[i];
    for (int i = tid; i < 64;     i += 256) sb1[i] = b1[i];
    for (int i = tid; i < 8 * 64; i += 256) {
        int q = i >> 6, l = i & 63;
        sHw[l][q] = Ww[i];
        sHs[l][q] = Ws[i];
    }
    for (int i = tid; i < 24 * 64; i += 256) {
        int r = i >> 6, l = i & 63;
        sHf[l][r] = Wf[i];
    }
    if (tid < 8)  { sbw[tid] = bw[tid]; sbs[tid] = bs[tid]; }
    if (tid < 24) { sbf[tid] = bf[tid]; }
    __syncthreads();

    int pl    = tid >> 3;
    int lane8 = tid & 7;
    int pg    = blockIdx.x * 32 + pl;
    int total = N + M;

    float P0 = 0.0f, P1 = 0.0f, P2 = 0.0f;
    int side = 0, pt = 0;
    bool valid = (pg < total);
    if (valid) {
        side = (pg < N) ? 0 : 1;
        pt   = (pg < N) ? pg : pg - N;
        const float* P = (pg < N) ? (x + 3 * pg) : (y + 3 * (pg - N));
        P0 = P[0]; P1 = P[1]; P2 = P[2];
    }

    {
        int lbase = lane8 * 8;
#pragma unroll
        for (int k = 0; k < 8; k++) {
            int l = lbase + k;
            float t = sb1[l];
            t = fmaf(sW1[l * 3 + 0], P0, t);
            t = fmaf(sW1[l * 3 + 1], P1, t);
            t = fmaf(sW1[l * 3 + 2], P2, t);
            sh_h[pl][l] = selu_f(t);
        }
    }
    __syncthreads();

    if (valid) {
        int q = lane8;
        float aw = sbw[q], as = sbs[q];
        float f0 = sbf[q * 3 + 0], f1 = sbf[q * 3 + 1], f2 = sbf[q * 3 + 2];
#pragma unroll
        for (int l = 0; l < 64; l++) {
            float hl = sh_h[pl][l];
            aw = fmaf(sHw[l][q], hl, aw);
            as = fmaf(sHs[l][q], hl, as);
            f0 = fmaf(sHf[l][q * 3 + 0], hl, f0);
            f1 = fmaf(sHf[l][q * 3 + 1], hl, f1);
            f2 = fmaf(sHf[l][q * 3 + 2], hl, f2);
        }

        float w  = softplus_f(aw);
        float s  = softplus_f(as);
        float g0 = softplus_f(f0);
        float g1 = softplus_f(f1);
        float g2 = softplus_f(f2);
        float phase = g0 * P0 + g1 * P1 + g2 * P2;

        const float TWO_PI  = 6.283185307179586f;
        const float ROOT4_2 = 1.1892071150027210f;  // 2^(1/4)
        float ang = TWO_PI * phase;
        float sv = __sinf(ang);
        float cv = __cosf(ang);
        float A = w * sqrtf(s) * ROOT4_2;

        g_feat[side][q][pt]      = A * cv;
        g_feat[side][8 + q][pt]  = A * sv;
        g_feat[side][16 + q][pt] = s * s;

        if (q == 0) {
            const float SQRT_LOG2E = 1.2011224087864498f;  // sqrt(log2(e))
            g_feat[side][24][pt] = P0 * SQRT_LOG2E;
            g_feat[side][25][pt] = P1 * SQRT_LOG2E;
            g_feat[side][26][pt] = P2 * SQRT_LOG2E;
        }
    }

    // PDL: all stores above are done; allow the dependent pair_kernel to run.
    asm volatile("griddepcontrol.launch_dependents;");
}

// ---------------------------------------------------------------------------
// Phase 2: pair kernel. 64x64 tile per 256-thread block, 4x4 micro-tile.
// Gibbs product r*exp2(-d2*r) fully in half2 over j-pairs.
// ---------------------------------------------------------------------------
__global__ void __launch_bounds__(256)
pair_kernel(float* __restrict__ out, int N, int M)
{
    __shared__ float   sfx[27][64];       // x: u(0-7) v(8-15) s2(16-23) c(24-26)
    __shared__ float   sfy_uv[16][64];    // y: u, v
    __shared__ float   sfy_c[3][64];      // y: scaled coords
    __shared__ __half2 sfy_s2h[8][32];    // y: s2 packed in j-pairs

    // PDL: wait for feat_kernel's g_feat stores to be visible.
    asm volatile("griddepcontrol.wait;");

    int tid = threadIdx.x;
    int i0 = blockIdx.y * 64;
    int j0 = blockIdx.x * 64;

    for (int idx = tid; idx < 27 * 64; idx += 256) {
        int r = idx >> 6, c = idx & 63;
        float pad = (r >= 16 && r < 24) ? 1.0f : 0.0f;
        int gi = i0 + c;
        sfx[r][c] = (gi < N) ? g_feat[0][r][gi] : pad;
    }
    for (int idx = tid; idx < 16 * 64; idx += 256) {
        int r = idx >> 6, c = idx & 63;
        int gj = j0 + c;
        sfy_uv[r][c] = (gj < M) ? g_feat[1][r][gj] : 0.0f;
    }
    for (int idx = tid; idx < 3 * 64; idx += 256) {
        int d = idx >> 6, c = idx & 63;
        int gj = j0 + c;
        sfy_c[d][c] = (gj < M) ? g_feat[1][24 + d][gj] : 0.0f;
    }
    {   // 8 rows x 32 half2 = 256 entries: one per thread
        int q = tid >> 5, c = tid & 31;
        int gj = j0 + 2 * c;
        float a = (gj     < M) ? g_feat[1][16 + q][gj]     : 1.0f;
        float b = (gj + 1 < M) ? g_feat[1][16 + q][gj + 1] : 1.0f;
        sfy_s2h[q][c] = __floats2half2_rn(a, b);
    }
    __syncthreads();

    int tx = tid & 15;      // j group
    int ty = tid >> 4;      // i group
    int ib = ty * 4;
    int jb = tx * 4;

    // d2h[ii][jp] = half2{-d2(ii,2jp), -d2(ii,2jp+1)}  (log2e in coords)
    __half2 d2h[4][2];
    {
        float4 px0 = *(const float4*)&sfx[24][ib];
        float4 px1 = *(const float4*)&sfx[25][ib];
        float4 px2 = *(const float4*)&sfx[26][ib];
        float4 py0 = *(const float4*)&sfy_c[0][jb];
        float4 py1 = *(const float4*)&sfy_c[1][jb];
        float4 py2 = *(const float4*)&sfy_c[2][jb];

        float xa0[4] = {px0.x, px0.y, px0.z, px0.w};
        float xa1[4] = {px1.x, px1.y, px1.z, px1.w};
        float xa2[4] = {px2.x, px2.y, px2.z, px2.w};
        float ya0[4] = {py0.x, py0.y, py0.z, py0.w};
        float ya1[4] = {py1.x, py1.y, py1.z, py1.w};
        float ya2[4] = {py2.x, py2.y, py2.z, py2.w};

#pragma unroll
        for (int ii = 0; ii < 4; ii++) {
            float t[4];
#pragma unroll
            for (int jj = 0; jj < 4; jj++) {
                float dx = xa0[ii] - ya0[jj];
                float dy = xa1[ii] - ya1[jj];
                float dz = xa2[ii] - ya2[jj];
                t[jj] = -fmaf(dx, dx, fmaf(dy, dy, dz * dz));
            }
            d2h[ii][0] = __floats2half2_rn(t[0], t[1]);
            d2h[ii][1] = __floats2half2_rn(t[2], t[3]);
        }
    }

    float acc[4][4];
#pragma unroll
    for (int ii = 0; ii < 4; ii++)
#pragma unroll
        for (int jj = 0; jj < 4; jj++) acc[ii][jj] = 0.0f;

#pragma unroll
    for (int q = 0; q < 8; q++) {
        float4 ux4 = *(const float4*)&sfx[q][ib];
        float4 vx4 = *(const float4*)&sfx[8 + q][ib];
        float4 wx4 = *(const float4*)&sfx[16 + q][ib];
        float4 uy4 = *(const float4*)&sfy_uv[q][jb];
        float4 vy4 = *(const float4*)&sfy_uv[8 + q][jb];

        float ux[4] = {ux4.x, ux4.y, ux4.z, ux4.w};
        float vx[4] = {vx4.x, vx4.y, vx4.z, vx4.w};
        float wx[4] = {wx4.x, wx4.y, wx4.z, wx4.w};
        float uy[4] = {uy4.x, uy4.y, uy4.z, uy4.w};
        float vy[4] = {vy4.x, vy4.y, vy4.z, vy4.w};

        // y-side s2 already packed as half2 pairs
        const __half2* wyp = &sfy_s2h[q][tx * 2];
        __half2 wyh0 = wyp[0];
        __half2 wyh1 = wyp[1];

#pragma unroll
        for (int ii = 0; ii < 4; ii++) {
            __half2 wxh = __float2half2_rn(wx[ii]);
#pragma unroll
            for (int jp = 0; jp < 2; jp++) {
                __half2 s2h = __hadd2(wxh, (jp == 0) ? wyh0 : wyh1);
                __half2 rh  = h2rcp_cubic(s2h);
                __half2 zh  = __hmul2(d2h[ii][jp], rh);
                __half2 eh  = h2exp2(zh);               // 1 MUFU / 2 pairs
                __half2 reh = __hmul2(rh, eh);          // r * e, fp16
                float2 ref  = __half22float2(reh);

                int j0i = jp * 2;
                float cc0 = fmaf(ux[ii], uy[j0i],     vx[ii] * vy[j0i]);
                float cc1 = fmaf(ux[ii], uy[j0i + 1], vx[ii] * vy[j0i + 1]);
                acc[ii][j0i]     = fmaf(cc0, ref.x, acc[ii][j0i]);
                acc[ii][j0i + 1] = fmaf(cc1, ref.y, acc[ii][j0i + 1]);
            }
        }
    }

#pragma unroll
    for (int ii = 0; ii < 4; ii++) {
        int i = i0 + ib + ii;
        if (i >= N) continue;
        int j = j0 + jb;
        if (j + 3 < M) {
            float4 v = make_float4(acc[ii][0], acc[ii][1], acc[ii][2], acc[ii][3]);
            *(float4*)&out[(size_t)i * M + j] = v;
        } else {
#pragma unroll
            for (int jj = 0; jj < 4; jj++)
                if (j + jj < M) out[(size_t)i * M + j + jj] = acc[ii][jj];
        }
    }
}

// ---------------------------------------------------------------------------
extern "C" void kernel_launch(void* const* d_in, const int* in_sizes, int n_in,
                              void* d_out, int out_size) {
    const float* x  = (const float*)d_in[0];
    const float* y  = (const float*)d_in[1];
    const float* W1 = (const float*)d_in[2];
    const float* b1 = (const float*)d_in[3];
    const float* Ww = (const float*)d_in[4];
    const float* bw = (const float*)d_in[5];
    const float* Wf = (const float*)d_in[6];
    const float* bf = (const float*)d_in[7];
    const float* Ws = (const float*)d_in[8];
    const float* bs = (const float*)d_in[9];
    float* out = (float*)d_out;

    int N = in_sizes[0] / 3;
    int M = in_sizes[1] / 3;

    int total = N + M;
    feat_kernel<<<(total + 31) / 32, 256>>>(x, y, W1, b1, Ww, bw, Wf, bf,
                                            Ws, bs, N, M);

    // Launch pair_kernel as a programmatic dependent of feat_kernel:
    // it may begin scheduling early; griddepcontrol.wait inside the kernel
    // blocks until feat_kernel's stores are visible.
    dim3 grid((M + 63) / 64, (N + 63) / 64);
    cudaLaunchConfig_t cfg = {};
    cfg.gridDim  = grid;
    cfg.blockDim = dim3(256, 1, 1);
    cfg.dynamicSmemBytes = 0;
    cfg.stream = 0;
    cudaLaunchAttribute attrs[1];
    attrs[0].id = cudaLaunchAttributeProgrammaticStreamSerialization;
    attrs[0].val.programmaticStreamSerializationAllowed = 1;
    cfg.attrs = attrs;
    cfg.numAttrs = 1;
    cudaLaunchKernelEx(&cfg, pair_kernel, out, N, M);
}

// round 12
// speedup vs baseline: 1.1168x; 1.1168x over previous
#include <cuda_runtime.h>
#include <cuda_fp16.h>
#include <math.h>

// ---------------------------------------------------------------------------
// NonstationaryGaussianSpectralMixtureKernel
// Phase 1 (per point): u = A*cos(2pi ph), v = A*sin(2pi ph), s2 = s^2,
//   A = w*sqrt(s)*2^(1/4);  coords stored pre-scaled by sqrt(log2e).
// Phase 2: K[i,j] = sum_q (uX uY + vX vY) * [r * exp2(-d2*r)], r=1/(s2X+s2Y).
// Inner loop is FULLY fp16x2 over j-pairs (HADD2/HFMA2/HMUL2 rt=2 but 2
// pairs per slot): 4.5 fma-class ops + 0.5 MUFU per (pair,q).
// x-side smem holds duplicated-half half2 (LDS.32 broadcast, no converts);
// y-side smem holds j-pair-packed half2. Accumulation fp16, split even/odd q,
// converted to fp32 once in the epilogue.
// Phases linked by Programmatic Dependent Launch.
// ---------------------------------------------------------------------------

#define MAXPTS 8192
// [side][row][point]; rows: q->u, 8+q->v, 16+q->s2, 24..26 -> scaled coords
__device__ float g_feat[2][27][MAXPTS];

__device__ __forceinline__ float fex2_fast(float x) {
    float r; asm("ex2.approx.f32 %0, %1;" : "=f"(r) : "f"(x)); return r;
}
__device__ __forceinline__ float flg2_fast(float x) {
    float r; asm("lg2.approx.f32 %0, %1;" : "=f"(r) : "f"(x)); return r;
}

// fp16x2 reciprocal: per-half magic seed + one Halley step.
// Valid for s2 in [6e-5, ~24000] (no cross-half borrow, no subnormals).
__device__ __forceinline__ __half2 h2rcp_cubic(__half2 x) {
    unsigned int xb = *reinterpret_cast<unsigned int*>(&x);
    unsigned int rb = 0x779D779Du - xb;
    __half2 r0 = *reinterpret_cast<__half2*>(&rb);
    __half2 t  = __hmul2(x, r0);
    const __half2 h3  = __float2half2_rn(3.0f);
    const __half2 hn3 = __float2half2_rn(-3.0f);
    __half2 p  = __hfma2(t, t, __hfma2(hn3, t, h3));
    return __hmul2(r0, p);
}

__device__ __forceinline__ float selu_f(float x) {
    const float scale = 1.0507009873554805f;
    const float sa    = 1.7580993408473766f;   // scale*alpha
    const float LOG2E = 1.4426950408889634f;
    float em1 = fex2_fast(x * LOG2E) - 1.0f;
    return (x > 0.0f) ? scale * x : sa * em1;
}
__device__ __forceinline__ float softplus_f(float x) {
    const float LOG2E = 1.4426950408889634f;
    const float LN2   = 0.6931471805599453f;
    float e = fex2_fast(-fabsf(x) * LOG2E);
    return fmaxf(x, 0.0f) + LN2 * flg2_fast(1.0f + e);
}

// ---------------------------------------------------------------------------
// Phase 1: 8 threads per point (one per q), 32 points per 256-thread block.
// ---------------------------------------------------------------------------
__global__ void __launch_bounds__(256)
feat_kernel(
    const float* __restrict__ x, const float* __restrict__ y,
    const float* __restrict__ W1, const float* __restrict__ b1,
    const float* __restrict__ Ww, const float* __restrict__ bw,
    const float* __restrict__ Wf, const float* __restrict__ bf,
    const float* __restrict__ Ws, const float* __restrict__ bs,
    int N, int M)
{
    __shared__ float sW1[64 * 3];
    __shared__ float sb1[64];
    __shared__ float sHw[64][9];
    __shared__ float sHs[64][9];
    __shared__ float sHf[64][25];
    __shared__ float sbw[8], sbs[8], sbf[24];
    __shared__ float sh_h[32][65];

    int tid = threadIdx.x;
    for (int i = tid; i < 64 * 3; i += 256) sW1[i] = W1[i];
    for (int i = tid; i < 64;     i += 256) sb1[i] = b1[i];
    for (int i = tid; i < 8 * 64; i += 256) {
        int q = i >> 6, l = i & 63;
        sHw[l][q] = Ww[i];
        sHs[l][q] = Ws[i];
    }
    for (int i = tid; i < 24 * 64; i += 256) {
        int r = i >> 6, l = i & 63;
        sHf[l][r] = Wf[i];
    }
    if (tid < 8)  { sbw[tid] = bw[tid]; sbs[tid] = bs[tid]; }
    if (tid < 24) { sbf[tid] = bf[tid]; }
    __syncthreads();

    int pl    = tid >> 3;
    int lane8 = tid & 7;
    int pg    = blockIdx.x * 32 + pl;
    int total = N + M;

    float P0 = 0.0f, P1 = 0.0f, P2 = 0.0f;
    int side = 0, pt = 0;
    bool valid = (pg < total);
    if (valid) {
        side = (pg < N) ? 0 : 1;
        pt   = (pg < N) ? pg : pg - N;
        const float* P = (pg < N) ? (x + 3 * pg) : (y + 3 * (pg - N));
        P0 = P[0]; P1 = P[1]; P2 = P[2];
    }

    {
        int lbase = lane8 * 8;
#pragma unroll
        for (int k = 0; k < 8; k++) {
            int l = lbase + k;
            float t = sb1[l];
            t = fmaf(sW1[l * 3 + 0], P0, t);
            t = fmaf(sW1[l * 3 + 1], P1, t);
            t = fmaf(sW1[l * 3 + 2], P2, t);
            sh_h[pl][l] = selu_f(t);
        }
    }
    __syncthreads();

    if (valid) {
        int q = lane8;
        float aw = sbw[q], as = sbs[q];
        float f0 = sbf[q * 3 + 0], f1 = sbf[q * 3 + 1], f2 = sbf[q * 3 + 2];
#pragma unroll
        for (int l = 0; l < 64; l++) {
            float hl = sh_h[pl][l];
            aw = fmaf(sHw[l][q], hl, aw);
            as = fmaf(sHs[l][q], hl, as);
            f0 = fmaf(sHf[l][q * 3 + 0], hl, f0);
            f1 = fmaf(sHf[l][q * 3 + 1], hl, f1);
            f2 = fmaf(sHf[l][q * 3 + 2], hl, f2);
        }

        float w  = softplus_f(aw);
        float s  = softplus_f(as);
        float g0 = softplus_f(f0);
        float g1 = softplus_f(f1);
        float g2 = softplus_f(f2);
        float phase = g0 * P0 + g1 * P1 + g2 * P2;

        const float TWO_PI  = 6.283185307179586f;
        const float ROOT4_2 = 1.1892071150027210f;  // 2^(1/4)
        float ang = TWO_PI * phase;
        float sv = __sinf(ang);
        float cv = __cosf(ang);
        float A = w * sqrtf(s) * ROOT4_2;

        g_feat[side][q][pt]      = A * cv;
        g_feat[side][8 + q][pt]  = A * sv;
        g_feat[side][16 + q][pt] = s * s;

        if (q == 0) {
            const float SQRT_LOG2E = 1.2011224087864498f;  // sqrt(log2(e))
            g_feat[side][24][pt] = P0 * SQRT_LOG2E;
            g_feat[side][25][pt] = P1 * SQRT_LOG2E;
            g_feat[side][26][pt] = P2 * SQRT_LOG2E;
        }
    }

    // PDL: all stores done; let the dependent pair_kernel proceed.
    asm volatile("griddepcontrol.launch_dependents;");
}

// ---------------------------------------------------------------------------
// Phase 2: pair kernel. 64x64 tile per 256-thread block, 4x4 micro-tile.
// Fully packed fp16x2 inner loop over j-pairs.
// ---------------------------------------------------------------------------
__global__ void __launch_bounds__(256)
pair_kernel(float* __restrict__ out, int N, int M)
{
    __shared__ __half2 sbx[24][64];   // x feats, value duplicated in both halves
    __shared__ __half2 sby[24][32];   // y feats, packed j-pairs
    __shared__ float   scx[3][64];    // x scaled coords (fp32)
    __shared__ float   scy[3][64];    // y scaled coords (fp32)

    // PDL: wait for feat_kernel's g_feat stores to be visible.
    asm volatile("griddepcontrol.wait;");

    int tid = threadIdx.x;
    int i0 = blockIdx.y * 64;
    int j0 = blockIdx.x * 64;

    // x-side: broadcast-packed half2
    for (int idx = tid; idx < 24 * 64; idx += 256) {
        int r = idx >> 6, c = idx & 63;
        float pad = (r >= 16) ? 1.0f : 0.0f;
        int gi = i0 + c;
        float v = (gi < N) ? g_feat[0][r][gi] : pad;
        sbx[r][c] = __half2half2(__float2half_rn(v));
    }
    // y-side: j-pair-packed half2  (24 rows x 32 pairs = 768 entries)
    for (int idx = tid; idx < 24 * 32; idx += 256) {
        int r = idx >> 5, c = idx & 31;
        float pad = (r >= 16) ? 1.0f : 0.0f;
        int gj = j0 + 2 * c;
        float a = (gj     < M) ? g_feat[1][r][gj]     : pad;
        float b = (gj + 1 < M) ? g_feat[1][r][gj + 1] : pad;
        sby[r][c] = __floats2half2_rn(a, b);
    }
    for (int idx = tid; idx < 3 * 64; idx += 256) {
        int d = idx >> 6, c = idx & 63;
        int gi = i0 + c;
        scx[d][c] = (gi < N) ? g_feat[0][24 + d][gi] : 0.0f;
        int gj = j0 + c;
        scy[d][c] = (gj < M) ? g_feat[1][24 + d][gj] : 0.0f;
    }
    __syncthreads();

    int tx = tid & 15;      // j group
    int ty = tid >> 4;      // i group
    int ib = ty * 4;
    int jb = tx * 4;

    // d2h[ii][jp] = half2{-d2(ii,2jp), -d2(ii,2jp+1)}  (log2e in coords)
    __half2 d2h[4][2];
    {
        float4 px0 = *(const float4*)&scx[0][ib];
        float4 px1 = *(const float4*)&scx[1][ib];
        float4 px2 = *(const float4*)&scx[2][ib];
        float4 py0 = *(const float4*)&scy[0][jb];
        float4 py1 = *(const float4*)&scy[1][jb];
        float4 py2 = *(const float4*)&scy[2][jb];

        float xa0[4] = {px0.x, px0.y, px0.z, px0.w};
        float xa1[4] = {px1.x, px1.y, px1.z, px1.w};
        float xa2[4] = {px2.x, px2.y, px2.z, px2.w};
        float ya0[4] = {py0.x, py0.y, py0.z, py0.w};
        float ya1[4] = {py1.x, py1.y, py1.z, py1.w};
        float ya2[4] = {py2.x, py2.y, py2.z, py2.w};

#pragma unroll
        for (int ii = 0; ii < 4; ii++) {
            float t[4];
#pragma unroll
            for (int jj = 0; jj < 4; jj++) {
                float dx = xa0[ii] - ya0[jj];
                float dy = xa1[ii] - ya1[jj];
                float dz = xa2[ii] - ya2[jj];
                t[jj] = -fmaf(dx, dx, fmaf(dy, dy, dz * dz));
            }
            d2h[ii][0] = __floats2half2_rn(t[0], t[1]);
            d2h[ii][1] = __floats2half2_rn(t[2], t[3]);
        }
    }

    // fp16 accumulators, split even/odd q
    __half2 accA[4][2], accB[4][2];
#pragma unroll
    for (int ii = 0; ii < 4; ii++)
#pragma unroll
        for (int jp = 0; jp < 2; jp++) {
            accA[ii][jp] = __float2half2_rn(0.0f);
            accB[ii][jp] = __float2half2_rn(0.0f);
        }

#pragma unroll
    for (int q = 0; q < 8; q++) {
        __half2 uy0 = sby[q][tx * 2],      uy1 = sby[q][tx * 2 + 1];
        __half2 vy0 = sby[8 + q][tx * 2],  vy1 = sby[8 + q][tx * 2 + 1];
        __half2 wy0 = sby[16 + q][tx * 2], wy1 = sby[16 + q][tx * 2 + 1];

#pragma unroll
        for (int ii = 0; ii < 4; ii++) {
            __half2 uxh = sbx[q][ib + ii];       // LDS.32 broadcast pair
            __half2 vxh = sbx[8 + q][ib + ii];
            __half2 wxh = sbx[16 + q][ib + ii];

#pragma unroll
            for (int jp = 0; jp < 2; jp++) {
                __half2 wyh = (jp == 0) ? wy0 : wy1;
                __half2 uyh = (jp == 0) ? uy0 : uy1;
                __half2 vyh = (jp == 0) ? vy0 : vy1;

                __half2 s2h = __hadd2(wxh, wyh);
                __half2 rh  = h2rcp_cubic(s2h);
                __half2 zh  = __hmul2(d2h[ii][jp], rh);
                __half2 eh  = h2exp2(zh);               // 1 MUFU / 2 pairs
                __half2 reh = __hmul2(rh, eh);
                __half2 cch = __hfma2(uxh, uyh, __hmul2(vxh, vyh));
                if (q & 1) accB[ii][jp] = __hfma2(cch, reh, accB[ii][jp]);
                else       accA[ii][jp] = __hfma2(cch, reh, accA[ii][jp]);
            }
        }
    }

    // epilogue: fp16 partials -> fp32, store
#pragma unroll
    for (int ii = 0; ii < 4; ii++) {
        int i = i0 + ib + ii;
        if (i >= N) continue;
        float2 a0 = __half22float2(accA[ii][0]);
        float2 b0 = __half22float2(accB[ii][0]);
        float2 a1 = __half22float2(accA[ii][1]);
        float2 b1 = __half22float2(accB[ii][1]);
        float r0 = a0.x + b0.x, r1 = a0.y + b0.y;
        float r2 = a1.x + b1.x, r3 = a1.y + b1.y;
        int j = j0 + jb;
        if (j + 3 < M) {
            *(float4*)&out[(size_t)i * M + j] = make_float4(r0, r1, r2, r3);
        } else {
            float av[4] = {r0, r1, r2, r3};
#pragma unroll
            for (int jj = 0; jj < 4; jj++)
                if (j + jj < M) out[(size_t)i * M + j + jj] = av[jj];
        }
    }
}

// ---------------------------------------------------------------------------
extern "C" void kernel_launch(void* const* d_in, const int* in_sizes, int n_in,
                              void* d_out, int out_size) {
    const float* x  = (const float*)d_in[0];
    const float* y  = (const float*)d_in[1];
    const float* W1 = (const float*)d_in[2];
    const float* b1 = (const float*)d_in[3];
    const float* Ww = (const float*)d_in[4];
    const float* bw = (const float*)d_in[5];
    const float* Wf = (const float*)d_in[6];
    const float* bf = (const float*)d_in[7];
    const float* Ws = (const float*)d_in[8];
    const float* bs = (const float*)d_in[9];
    float* out = (float*)d_out;

    int N = in_sizes[0] / 3;
    int M = in_sizes[1] / 3;

    int total = N + M;
    feat_kernel<<<(total + 31) / 32, 256>>>(x, y, W1, b1, Ww, bw, Wf, bf,
                                            Ws, bs, N, M);

    dim3 grid((M + 63) / 64, (N + 63) / 64);
    cudaLaunchConfig_t cfg = {};
    cfg.gridDim  = grid;
    cfg.blockDim = dim3(256, 1, 1);
    cfg.dynamicSmemBytes = 0;
    cfg.stream = 0;
    cudaLaunchAttribute attrs[1];
    attrs[0].id = cudaLaunchAttributeProgrammaticStreamSerialization;
    attrs[0].val.programmaticStreamSerializationAllowed = 1;
    cfg.attrs = attrs;
    cfg.numAttrs = 1;
    cudaLaunchKernelEx(&cfg, pair_kernel, out, N, M);
}